// round 3
// baseline (speedup 1.0000x reference)
#include <cuda_runtime.h>

#define N_NODES 100000
#define N_EDGES 1600000
#define F 128

// ---------------- scratch (device globals; no runtime allocation) ----------
__device__ float g_dinv[N_NODES];            // degree -> rsqrt(degree) in place
__device__ float g_h[(size_t)N_NODES * F];   // GEMM output
__device__ float g_a[(size_t)N_NODES * F];   // aggregation output / layer output
__device__ float g_pool[F];                  // mean-pool accumulator

// ---------------- degree / normalization -----------------------------------
__global__ void k_deg_init(float* deg) {
    int i = blockIdx.x * blockDim.x + threadIdx.x;
    if (i < N_NODES) deg[i] = 1.0f;          // self-loop contributes 1
}

__global__ void k_deg_count(const int* __restrict__ dst, float* deg) {
    int e = blockIdx.x * blockDim.x + threadIdx.x;
    if (e < N_EDGES) atomicAdd(&deg[dst[e]], 1.0f);
}

__global__ void k_rsqrt_inplace(float* deg) {
    int i = blockIdx.x * blockDim.x + threadIdx.x;
    if (i < N_NODES) deg[i] = rsqrtf(deg[i]);
}

// ---------------- SGEMM: Out[M,128] = X[M,128] @ W[128,128] -----------------
// 64x128 block tile, 256 threads, each thread 8x4 micro-tile.
__global__ void __launch_bounds__(256) k_gemm(const float* __restrict__ X,
                                              const float* __restrict__ W,
                                              float* __restrict__ Out, int M) {
    __shared__ float xs[16][68];    // [kk][row], padded stride 68 (16B-aligned)
    __shared__ float ws[16][128];   // [kk][n]

    const int tid = threadIdx.x;
    const int tx  = tid & 31;       // col group: cols tx*4 .. tx*4+3
    const int ty  = tid >> 5;       // row group: rows ty*8 .. ty*8+7
    const int bm  = blockIdx.x * 64;

    float acc[8][4];
#pragma unroll
    for (int i = 0; i < 8; i++)
#pragma unroll
        for (int j = 0; j < 4; j++) acc[i][j] = 0.0f;

    const int r = tid >> 2;         // 0..63 (x-tile row this thread loads)
    const int c = tid & 3;          // 0..3  (k sub-chunk)

    for (int k0 = 0; k0 < 128; k0 += 16) {
        // load X tile (64 x 16), transposed into xs[kk][row]
        float4 xv = make_float4(0.f, 0.f, 0.f, 0.f);
        int grow = bm + r;
        if (grow < M)
            xv = *(const float4*)&X[(size_t)grow * F + k0 + c * 4];
        xs[c * 4 + 0][r] = xv.x;
        xs[c * 4 + 1][r] = xv.y;
        xs[c * 4 + 2][r] = xv.z;
        xs[c * 4 + 3][r] = xv.w;

        // load W tile (16 x 128): 512 float4, 2 per thread
#pragma unroll
        for (int t = 0; t < 2; t++) {
            int fid = tid + t * 256;        // 0..511
            int kk  = fid >> 5;             // 32 float4 per row
            int n4  = fid & 31;
            *(float4*)&ws[kk][n4 * 4] =
                *(const float4*)&W[(size_t)(k0 + kk) * F + n4 * 4];
        }
        __syncthreads();

#pragma unroll
        for (int kk = 0; kk < 16; kk++) {
            float4 b  = *(float4*)&ws[kk][tx * 4];
            float4 a0 = *(float4*)&xs[kk][ty * 8];
            float4 a1 = *(float4*)&xs[kk][ty * 8 + 4];
            float ar[8] = {a0.x, a0.y, a0.z, a0.w, a1.x, a1.y, a1.z, a1.w};
#pragma unroll
            for (int i = 0; i < 8; i++) {
                acc[i][0] = fmaf(ar[i], b.x, acc[i][0]);
                acc[i][1] = fmaf(ar[i], b.y, acc[i][1]);
                acc[i][2] = fmaf(ar[i], b.z, acc[i][2]);
                acc[i][3] = fmaf(ar[i], b.w, acc[i][3]);
            }
        }
        __syncthreads();
    }

#pragma unroll
    for (int i = 0; i < 8; i++) {
        int grow = bm + ty * 8 + i;
        if (grow < M)
            *(float4*)&Out[(size_t)grow * F + tx * 4] =
                make_float4(acc[i][0], acc[i][1], acc[i][2], acc[i][3]);
    }
}

// ---------------- aggregation ----------------------------------------------
// self-loop term (non-atomic init): a[i] = h[i] * dinv[i]^2
__global__ void k_self(const float* __restrict__ h, const float* __restrict__ dinv,
                       float* __restrict__ a) {
    int idx = blockIdx.x * blockDim.x + threadIdx.x;   // N_NODES * 32
    int node = idx >> 5;
    int l    = idx & 31;
    if (node < N_NODES) {
        float w = dinv[node];
        w *= w;
        float4 v = *(const float4*)&h[(size_t)node * F + l * 4];
        v.x *= w; v.y *= w; v.z *= w; v.w *= w;
        *(float4*)&a[(size_t)node * F + l * 4] = v;
    }
}

// warp per edge: a[dst] += h[src] * dinv[src]*dinv[dst]   (float4 RED)
__global__ void __launch_bounds__(256) k_edges(const int* __restrict__ src,
                                               const int* __restrict__ dst,
                                               const float* __restrict__ dinv,
                                               const float* __restrict__ h,
                                               float* __restrict__ a) {
    int gid  = blockIdx.x * blockDim.x + threadIdx.x;
    int e    = gid >> 5;
    int lane = gid & 31;
    if (e >= N_EDGES) return;
    int s = __ldg(&src[e]);
    int d = __ldg(&dst[e]);
    float w = dinv[s] * dinv[d];
    float4 v = *(const float4*)&h[(size_t)s * F + lane * 4];
    v.x *= w; v.y *= w; v.z *= w; v.w *= w;
#if __CUDA_ARCH__ >= 900
    atomicAdd((float4*)&a[(size_t)d * F + lane * 4], v);
#else
    float* p = &a[(size_t)d * F + lane * 4];
    atomicAdd(p + 0, v.x); atomicAdd(p + 1, v.y);
    atomicAdd(p + 2, v.z); atomicAdd(p + 3, v.w);
#endif
}

// a = relu(a + bias)
__global__ void k_bias_relu(float* __restrict__ a, const float* __restrict__ b) {
    int idx = blockIdx.x * blockDim.x + threadIdx.x;   // N_NODES * 32 (float4)
    if (idx >= N_NODES * 32) return;
    int f4 = idx & 31;
    float4 bb = *(const float4*)&b[f4 * 4];
    float4 v  = *(float4*)&a[(size_t)idx * 4];
    v.x = fmaxf(v.x + bb.x, 0.f);
    v.y = fmaxf(v.y + bb.y, 0.f);
    v.z = fmaxf(v.z + bb.z, 0.f);
    v.w = fmaxf(v.w + bb.w, 0.f);
    *(float4*)&a[(size_t)idx * 4] = v;
}

// ---------------- pooling + FC ----------------------------------------------
__global__ void k_pool_init(float* pool) {
    if (threadIdx.x < F) pool[threadIdx.x] = 0.0f;
}

__global__ void k_pool(const float* __restrict__ a, float* __restrict__ pool) {
    int f = threadIdx.x;                    // 128 threads
    float s = 0.0f;
    for (int rr = blockIdx.x; rr < N_NODES; rr += gridDim.x)
        s += a[(size_t)rr * F + f];
    atomicAdd(&pool[f], s);
}

__global__ void k_fc(const float* __restrict__ pool, const float* __restrict__ fw,
                     const float* __restrict__ fb, float* __restrict__ out) {
    int j = threadIdx.x;
    if (j < 2) {
        const float inv_n = 1.0f / (float)N_NODES;
        float s = 0.0f;
        for (int k = 0; k < F; k++)
            s += pool[k] * inv_n * fw[k * 2 + j];
        out[j] = s + fb[j];
    }
}

// ---------------- launch -----------------------------------------------------
extern "C" void kernel_launch(void* const* d_in, const int* in_sizes, int n_in,
                              void* d_out, int out_size) {
    const float* x    = (const float*)d_in[0];
    const int*   eidx = (const int*)d_in[1];     // (2, N_EDGES)
    const float* W1   = (const float*)d_in[2];
    const float* b1   = (const float*)d_in[3];
    const float* W2   = (const float*)d_in[4];
    const float* b2   = (const float*)d_in[5];
    const float* W3   = (const float*)d_in[6];
    const float* b3   = (const float*)d_in[7];
    const float* fcw  = (const float*)d_in[8];
    const float* fcb  = (const float*)d_in[9];
    float* out = (float*)d_out;

    const int* e_src = eidx;
    const int* e_dst = eidx + N_EDGES;

    float *dinv, *h, *a, *pool;
    cudaGetSymbolAddress((void**)&dinv, g_dinv);
    cudaGetSymbolAddress((void**)&h,    g_h);
    cudaGetSymbolAddress((void**)&a,    g_a);
    cudaGetSymbolAddress((void**)&pool, g_pool);

    // degree + rsqrt
    k_deg_init<<<(N_NODES + 255) / 256, 256>>>(dinv);
    k_deg_count<<<(N_EDGES + 255) / 256, 256>>>(e_dst, dinv);
    k_rsqrt_inplace<<<(N_NODES + 255) / 256, 256>>>(dinv);

    const int gemm_grid = (N_NODES + 63) / 64;
    const int node_f4   = (N_NODES * 32 + 255) / 256;
    const int edge_grid = (N_EDGES * 32 + 255) / 256;

    const float* Ws[3] = {W1, W2, W3};
    const float* bs[3] = {b1, b2, b3};

    for (int layer = 0; layer < 3; layer++) {
        const float* in = (layer == 0) ? x : a;
        k_gemm<<<gemm_grid, 256>>>(in, Ws[layer], h, N_NODES);
        k_self<<<node_f4, 256>>>(h, dinv, a);
        k_edges<<<edge_grid, 256>>>(e_src, e_dst, dinv, h, a);
        k_bias_relu<<<node_f4, 256>>>(a, bs[layer]);
    }

    k_pool_init<<<1, 128>>>(pool);
    k_pool<<<1024, 128>>>(a, pool);
    k_fc<<<1, 32>>>(pool, fcw, fcb, out);
}

// round 7
// speedup vs baseline: 1.6763x; 1.6763x over previous
#include <cuda_runtime.h>

#define N_NODES 100000
#define N_EDGES 1600000
#define F 128
#define NCHUNK 1000
#define CHUNK 100

// ---------------- scratch (device globals; no runtime allocation) ----------
__device__ int   g_cnt[N_NODES];       // degree count, then CSR cursor, ends as row end
__device__ int   g_rowptr[N_NODES];    // CSR row start
__device__ int   g_chunksums[1024];
__device__ int2  g_edge[N_EDGES];      // packed {src, weight-as-int-bits}, sorted by dst
__device__ float g_dinv[N_NODES];
__device__ float g_h[(size_t)N_NODES * F];
__device__ float g_a[(size_t)N_NODES * F];
__device__ float g_pool[F];

// ---------------- init / degree ---------------------------------------------
__global__ void k_zero() {
    int i = blockIdx.x * blockDim.x + threadIdx.x;
    if (i < N_NODES) g_cnt[i] = 0;
    if (i < F) g_pool[i] = 0.0f;
}

__global__ void k_hist(const int* __restrict__ dst) {
    int e = blockIdx.x * blockDim.x + threadIdx.x;
    if (e < N_EDGES) atomicAdd(&g_cnt[dst[e]], 1);
}

__global__ void k_dinv() {
    int i = blockIdx.x * blockDim.x + threadIdx.x;
    if (i < N_NODES) g_dinv[i] = rsqrtf(1.0f + (float)g_cnt[i]);  // +1 self-loop
}

// ---------------- 2-level exclusive scan of g_cnt -> g_rowptr ----------------
__global__ void k_scanA() {
    int c = blockIdx.x * blockDim.x + threadIdx.x;
    if (c < NCHUNK) {
        int s = 0, base = c * CHUNK;
        for (int i = 0; i < CHUNK; i++) s += g_cnt[base + i];
        g_chunksums[c] = s;
    }
}

__global__ void k_scanB() {   // single block of 1024: exclusive scan of chunk sums
    __shared__ int sh[1024];
    int t = threadIdx.x;
    int v = (t < NCHUNK) ? g_chunksums[t] : 0;
    sh[t] = v;
    __syncthreads();
    for (int off = 1; off < 1024; off <<= 1) {
        int x = sh[t];
        if (t >= off) x += sh[t - off];
        __syncthreads();
        sh[t] = x;
        __syncthreads();
    }
    if (t < NCHUNK) g_chunksums[t] = sh[t] - v;   // exclusive
}

__global__ void k_scanC() {
    int c = blockIdx.x * blockDim.x + threadIdx.x;
    if (c < NCHUNK) {
        int run = g_chunksums[c], base = c * CHUNK;
        for (int i = 0; i < CHUNK; i++) {
            int idx = base + i;
            int cc = g_cnt[idx];
            g_rowptr[idx] = run;
            g_cnt[idx] = run;      // cursor for fill (ends equal to row end)
            run += cc;
        }
    }
}

__global__ void k_fill(const int* __restrict__ src, const int* __restrict__ dst) {
    int e = blockIdx.x * blockDim.x + threadIdx.x;
    if (e >= N_EDGES) return;
    int s = __ldg(&src[e]);
    int d = __ldg(&dst[e]);
    int pos = atomicAdd(&g_cnt[d], 1);
    float w = g_dinv[s] * g_dinv[d];
    g_edge[pos] = make_int2(s, __float_as_int(w));
}

// ---------------- SGEMM: Out[M,128] = X[M,128] @ W[128,128] -----------------
// 128x128 block tile, 256 threads, 8x8 micro-tile (split 4+4 rows/cols).
__global__ void __launch_bounds__(256) k_gemm(const float* __restrict__ X,
                                              const float* __restrict__ W,
                                              float* __restrict__ Out, int M) {
    __shared__ float xs[16][128];   // [kk][row], rows XOR-swizzled by (kk>>2)<<3
    __shared__ float ws[16][128];   // [kk][n]

    const int tid = threadIdx.x;
    const int tx  = tid & 15;       // col quad: tx*4 and 64+tx*4
    const int ty  = tid >> 4;       // row quad: ty*4 and 64+ty*4
    const int bm  = blockIdx.x * 128;

    float acc[8][8];
#pragma unroll
    for (int i = 0; i < 8; i++)
#pragma unroll
        for (int j = 0; j < 8; j++) acc[i][j] = 0.0f;

    for (int k0 = 0; k0 < 128; k0 += 16) {
        // X tile: 128 rows x 16 k, transposed+swizzled. 512 float4, 2/thread.
#pragma unroll
        for (int t = 0; t < 2; t++) {
            int fid = tid + t * 256;
            int row = fid >> 2;         // 0..127
            int c   = fid & 3;          // k sub-chunk (= kk>>2)
            float4 xv = make_float4(0.f, 0.f, 0.f, 0.f);
            int gr = bm + row;
            if (gr < M) xv = *(const float4*)&X[(size_t)gr * F + k0 + c * 4];
            int sr = row ^ (c << 3);    // swizzle: conflict-free STS
            xs[c * 4 + 0][sr] = xv.x;
            xs[c * 4 + 1][sr] = xv.y;
            xs[c * 4 + 2][sr] = xv.z;
            xs[c * 4 + 3][sr] = xv.w;
        }
        // W tile: 16 x 128. 512 float4, 2/thread.
#pragma unroll
        for (int t = 0; t < 2; t++) {
            int fid = tid + t * 256;
            int kk  = fid >> 5;
            int n4  = fid & 31;
            *(float4*)&ws[kk][n4 * 4] =
                *(const float4*)&W[(size_t)(k0 + kk) * F + n4 * 4];
        }
        __syncthreads();

#pragma unroll
        for (int kk = 0; kk < 16; kk++) {
            const int sw = (kk >> 2) << 3;
            float4 a0 = *(float4*)&xs[kk][(ty * 4) ^ sw];
            float4 a1 = *(float4*)&xs[kk][(64 + ty * 4) ^ sw];
            float4 b0 = *(float4*)&ws[kk][tx * 4];
            float4 b1 = *(float4*)&ws[kk][64 + tx * 4];
            float av[8] = {a0.x, a0.y, a0.z, a0.w, a1.x, a1.y, a1.z, a1.w};
            float bv[8] = {b0.x, b0.y, b0.z, b0.w, b1.x, b1.y, b1.z, b1.w};
#pragma unroll
            for (int i = 0; i < 8; i++)
#pragma unroll
                for (int j = 0; j < 8; j++)
                    acc[i][j] = fmaf(av[i], bv[j], acc[i][j]);
        }
        __syncthreads();
    }

#pragma unroll
    for (int i = 0; i < 8; i++) {
        int gr = bm + ((i < 4) ? (ty * 4 + i) : (64 + ty * 4 + (i - 4)));
        if (gr < M) {
            *(float4*)&Out[(size_t)gr * F + tx * 4] =
                make_float4(acc[i][0], acc[i][1], acc[i][2], acc[i][3]);
            *(float4*)&Out[(size_t)gr * F + 64 + tx * 4] =
                make_float4(acc[i][4], acc[i][5], acc[i][6], acc[i][7]);
        }
    }
}

// ---------------- fused aggregation: a = relu(CSR_agg(h) + self + bias) ------
// warp per node; 8 nodes per block. POOL: accumulate into g_pool instead of a.
template <bool POOL>
__global__ void __launch_bounds__(256) k_agg(const float* __restrict__ h,
                                             const float* __restrict__ bias,
                                             float* __restrict__ a) {
    __shared__ float sp[8][F];   // used only when POOL
    const int warp = threadIdx.x >> 5;
    const int lane = threadIdx.x & 31;
    const int node = blockIdx.x * 8 + warp;

    float4 acc = make_float4(0.f, 0.f, 0.f, 0.f);
    const bool valid = node < N_NODES;

    if (valid) {
        float di = g_dinv[node];
        float ws = di * di;
        float4 v = *(const float4*)&h[(size_t)node * F + lane * 4];
        acc.x = v.x * ws; acc.y = v.y * ws; acc.z = v.z * ws; acc.w = v.w * ws;

        int j   = g_rowptr[node];
        int end = g_cnt[node];          // cursor landed at row end after fill
#pragma unroll 4
        for (; j < end; j++) {
            int2 er = __ldg(&g_edge[j]);
            float w = __int_as_float(er.y);
            float4 u = *(const float4*)&h[(size_t)er.x * F + lane * 4];
            acc.x = fmaf(w, u.x, acc.x);
            acc.y = fmaf(w, u.y, acc.y);
            acc.z = fmaf(w, u.z, acc.z);
            acc.w = fmaf(w, u.w, acc.w);
        }
        float4 bb = *(const float4*)&bias[lane * 4];
        acc.x = fmaxf(acc.x + bb.x, 0.f);
        acc.y = fmaxf(acc.y + bb.y, 0.f);
        acc.z = fmaxf(acc.z + bb.z, 0.f);
        acc.w = fmaxf(acc.w + bb.w, 0.f);
    }

    if (!POOL) {
        if (valid)
            *(float4*)&a[(size_t)node * F + lane * 4] = acc;
    } else {
        *(float4*)&sp[warp][lane * 4] = acc;   // invalid warps wrote zeros? acc=0 if !valid
        __syncthreads();
        if (threadIdx.x < F) {
            float s = 0.f;
#pragma unroll
            for (int w = 0; w < 8; w++) s += sp[w][threadIdx.x];
            atomicAdd(&g_pool[threadIdx.x], s);
        }
    }
}

// ---------------- FC ---------------------------------------------------------
__global__ void k_fc(const float* __restrict__ fw, const float* __restrict__ fb,
                     float* __restrict__ out) {
    int jj = threadIdx.x;
    if (jj < 2) {
        const float inv_n = 1.0f / (float)N_NODES;
        float s = 0.0f;
        for (int k = 0; k < F; k++)
            s += g_pool[k] * inv_n * fw[k * 2 + jj];
        out[jj] = s + fb[jj];
    }
}

// ---------------- launch -----------------------------------------------------
extern "C" void kernel_launch(void* const* d_in, const int* in_sizes, int n_in,
                              void* d_out, int out_size) {
    const float* x   = (const float*)d_in[0];
    const int*   ei  = (const int*)d_in[1];     // (2, N_EDGES)
    const float* W1  = (const float*)d_in[2];
    const float* b1  = (const float*)d_in[3];
    const float* W2  = (const float*)d_in[4];
    const float* b2  = (const float*)d_in[5];
    const float* W3  = (const float*)d_in[6];
    const float* b3  = (const float*)d_in[7];
    const float* fcw = (const float*)d_in[8];
    const float* fcb = (const float*)d_in[9];
    float* out = (float*)d_out;

    const int* e_src = ei;
    const int* e_dst = ei + N_EDGES;

    float *h, *a;
    cudaGetSymbolAddress((void**)&h, g_h);
    cudaGetSymbolAddress((void**)&a, g_a);

    // ---- CSR build (once per launch) ----
    k_zero<<<(N_NODES + 255) / 256, 256>>>();
    k_hist<<<(N_EDGES + 255) / 256, 256>>>(e_dst);
    k_dinv<<<(N_NODES + 255) / 256, 256>>>();
    k_scanA<<<(NCHUNK + 255) / 256, 256>>>();
    k_scanB<<<1, 1024>>>();
    k_scanC<<<(NCHUNK + 255) / 256, 256>>>();
    k_fill<<<(N_EDGES + 255) / 256, 256>>>(e_src, e_dst);

    const int gemm_grid = (N_NODES + 127) / 128;
    const int agg_grid  = (N_NODES + 7) / 8;

    // layer 1
    k_gemm<<<gemm_grid, 256>>>(x, W1, h, N_NODES);
    k_agg<false><<<agg_grid, 256>>>(h, b1, a);
    // layer 2
    k_gemm<<<gemm_grid, 256>>>(a, W2, h, N_NODES);
    k_agg<false><<<agg_grid, 256>>>(h, b2, a);
    // layer 3 (fused mean-pool accumulate)
    k_gemm<<<gemm_grid, 256>>>(a, W3, h, N_NODES);
    k_agg<true><<<agg_grid, 256>>>(h, b3, a);

    k_fc<<<1, 32>>>(fcw, fcb, out);
}

// round 9
// speedup vs baseline: 2.2194x; 1.3240x over previous
#include <cuda_runtime.h>
#include <cuda_fp16.h>

#define N_NODES 100000
#define N_EDGES 1600000
#define F 128
#define CHUNK 128
#define NCHUNK ((N_NODES + CHUNK - 1) / CHUNK)   // 782

// ---------------- scratch (device globals; no runtime allocation) ----------
__device__ int    g_cnt[N_NODES];       // degree count -> CSR cursor -> row end
__device__ int    g_rowptr[N_NODES];    // CSR row start
__device__ int    g_chunksums[1024];
__device__ int    g_esrc[N_EDGES];      // edge sources, grouped by dst
__device__ float  g_dinv[N_NODES];
__device__ __half g_feat16[(size_t)N_NODES * F];  // fp16 node features (layer in)
__device__ float  g_t[(size_t)N_NODES * F];       // fp32 aggregated features
__device__ float  g_pool[F];

// ---------------- init / degree ---------------------------------------------
__global__ void k_zero() {
    int i = blockIdx.x * blockDim.x + threadIdx.x;
    if (i < N_NODES) g_cnt[i] = 0;
    if (i < F) g_pool[i] = 0.0f;
}

__global__ void k_hist(const int* __restrict__ dst) {
    int e = blockIdx.x * blockDim.x + threadIdx.x;
    if (e < N_EDGES) atomicAdd(&g_cnt[dst[e]], 1);
}

__global__ void k_dinv() {
    int i = blockIdx.x * blockDim.x + threadIdx.x;
    if (i < N_NODES) g_dinv[i] = rsqrtf(1.0f + (float)g_cnt[i]);  // +1 self-loop
}

// ---------------- CSR scan: warp-parallel 3 phase ----------------------------
__global__ void k_scanA() {   // warp per chunk: sum CHUNK counts
    int warp = (blockIdx.x * blockDim.x + threadIdx.x) >> 5;
    int lane = threadIdx.x & 31;
    if (warp >= NCHUNK) return;
    int base = warp * CHUNK + lane * 4;
    int s = 0;
#pragma unroll
    for (int j = 0; j < 4; j++) {
        int idx = base + j;
        if (idx < N_NODES) s += g_cnt[idx];
    }
#pragma unroll
    for (int off = 16; off > 0; off >>= 1)
        s += __shfl_down_sync(0xffffffffu, s, off);
    if (lane == 0) g_chunksums[warp] = s;
}

__global__ void k_scanB() {   // 1 block: exclusive scan of chunk sums
    __shared__ int sh[1024];
    int t = threadIdx.x;
    int v = (t < NCHUNK) ? g_chunksums[t] : 0;
    sh[t] = v;
    __syncthreads();
    for (int off = 1; off < 1024; off <<= 1) {
        int x = sh[t];
        if (t >= off) x += sh[t - off];
        __syncthreads();
        sh[t] = x;
        __syncthreads();
    }
    if (t < NCHUNK) g_chunksums[t] = sh[t] - v;   // exclusive
}

__global__ void k_scanC() {   // warp per chunk: element-wise exclusive prefix
    int warp = (blockIdx.x * blockDim.x + threadIdx.x) >> 5;
    int lane = threadIdx.x & 31;
    if (warp >= NCHUNK) return;
    int base = warp * CHUNK + lane * 4;
    int v[4];
#pragma unroll
    for (int j = 0; j < 4; j++) {
        int idx = base + j;
        v[j] = (idx < N_NODES) ? g_cnt[idx] : 0;
    }
    int t1 = v[0], t2 = t1 + v[1], t3 = t2 + v[2], tot = t3 + v[3];
    int x = tot;
#pragma unroll
    for (int off = 1; off < 32; off <<= 1) {
        int y = __shfl_up_sync(0xffffffffu, x, off);
        if (lane >= off) x += y;
    }
    int b = g_chunksums[warp] + (x - tot);   // exclusive prefix for v[0]
    int pre[4] = {b, b + t1, b + t2, b + t3};
#pragma unroll
    for (int j = 0; j < 4; j++) {
        int idx = base + j;
        if (idx < N_NODES) { g_rowptr[idx] = pre[j]; g_cnt[idx] = pre[j]; }
    }
}

__global__ void k_fill(const int* __restrict__ src, const int* __restrict__ dst) {
    int e = blockIdx.x * blockDim.x + threadIdx.x;
    if (e >= N_EDGES) return;
    int d = __ldg(&dst[e]);
    int pos = atomicAdd(&g_cnt[d], 1);
    g_esrc[pos] = __ldg(&src[e]);
}

// ---------------- x -> fp16 --------------------------------------------------
__global__ void k_cvt(const float* __restrict__ x) {
    int idx = blockIdx.x * blockDim.x + threadIdx.x;   // N_NODES*32 float4 units
    if (idx >= N_NODES * 32) return;
    float4 v = *(const float4*)&x[(size_t)idx * 4];
    __half2 h0 = __floats2half2_rn(v.x, v.y);
    __half2 h1 = __floats2half2_rn(v.z, v.w);
    uint2 r;
    r.x = *reinterpret_cast<unsigned*>(&h0);
    r.y = *reinterpret_cast<unsigned*>(&h1);
    *reinterpret_cast<uint2*>(&g_feat16[(size_t)idx * 4]) = r;
}

// ---------------- aggregation: t = Â * feat16 (fp32 accum) -------------------
// warp per node; lane covers 4 features (8B fp16 loads).
__global__ void __launch_bounds__(256) k_agg() {
    const int warp = threadIdx.x >> 5;
    const int lane = threadIdx.x & 31;
    const int node = blockIdx.x * 8 + warp;
    if (node >= N_NODES) return;

    const __half* in16 = g_feat16;
    const float di = g_dinv[node];

    float4 acc;
    {   // self term, weight di (outer di applied at the end)
        uint2 r = __ldg((const uint2*)(in16 + (size_t)node * F + lane * 4));
        float2 f0 = __half22float2(*reinterpret_cast<__half2*>(&r.x));
        float2 f1 = __half22float2(*reinterpret_cast<__half2*>(&r.y));
        acc.x = di * f0.x; acc.y = di * f0.y;
        acc.z = di * f1.x; acc.w = di * f1.y;
    }

    int j   = g_rowptr[node];
    int end = g_cnt[node];
#pragma unroll 4
    for (; j < end; j++) {
        int s = __ldg(&g_esrc[j]);
        float w = __ldg(&g_dinv[s]);
        uint2 r = __ldg((const uint2*)(in16 + (size_t)s * F + lane * 4));
        float2 f0 = __half22float2(*reinterpret_cast<__half2*>(&r.x));
        float2 f1 = __half22float2(*reinterpret_cast<__half2*>(&r.y));
        acc.x = fmaf(w, f0.x, acc.x);
        acc.y = fmaf(w, f0.y, acc.y);
        acc.z = fmaf(w, f1.x, acc.z);
        acc.w = fmaf(w, f1.y, acc.w);
    }
    acc.x *= di; acc.y *= di; acc.z *= di; acc.w *= di;
    *(float4*)&g_t[(size_t)node * F + lane * 4] = acc;
}

// ---------------- SGEMM: relu(T[M,128] @ W[128,128] + b) ---------------------
// 128x128 tile, 256 threads, 8x8 micro-tile. Epilogue: fp16 store, or pool.
template <bool POOL>
__global__ void __launch_bounds__(256) k_gemm(const float* __restrict__ X,
                                              const float* __restrict__ W,
                                              const float* __restrict__ bias,
                                              __half* __restrict__ Out, int M) {
    __shared__ float xs[16][128];   // [kk][row], rows XOR-swizzled by (kk>>2)<<3
    __shared__ float ws[16][128];   // [kk][n]
    __shared__ float spool[F];      // POOL only

    const int tid = threadIdx.x;
    const int tx  = tid & 15;
    const int ty  = tid >> 4;
    const int bm  = blockIdx.x * 128;

    float acc[8][8];
#pragma unroll
    for (int i = 0; i < 8; i++)
#pragma unroll
        for (int j = 0; j < 8; j++) acc[i][j] = 0.0f;

    if (POOL) {
        if (tid < F) spool[tid] = 0.0f;
    }

    for (int k0 = 0; k0 < 128; k0 += 16) {
#pragma unroll
        for (int t = 0; t < 2; t++) {
            int fid = tid + t * 256;
            int row = fid >> 2;
            int c   = fid & 3;
            float4 xv = make_float4(0.f, 0.f, 0.f, 0.f);
            int gr = bm + row;
            if (gr < M) xv = *(const float4*)&X[(size_t)gr * F + k0 + c * 4];
            int sr = row ^ (c << 3);
            xs[c * 4 + 0][sr] = xv.x;
            xs[c * 4 + 1][sr] = xv.y;
            xs[c * 4 + 2][sr] = xv.z;
            xs[c * 4 + 3][sr] = xv.w;
        }
#pragma unroll
        for (int t = 0; t < 2; t++) {
            int fid = tid + t * 256;
            int kk  = fid >> 5;
            int n4  = fid & 31;
            *(float4*)&ws[kk][n4 * 4] =
                *(const float4*)&W[(size_t)(k0 + kk) * F + n4 * 4];
        }
        __syncthreads();

#pragma unroll
        for (int kk = 0; kk < 16; kk++) {
            const int sw = (kk >> 2) << 3;
            float4 a0 = *(float4*)&xs[kk][(ty * 4) ^ sw];
            float4 a1 = *(float4*)&xs[kk][(64 + ty * 4) ^ sw];
            float4 b0 = *(float4*)&ws[kk][tx * 4];
            float4 b1 = *(float4*)&ws[kk][64 + tx * 4];
            float av[8] = {a0.x, a0.y, a0.z, a0.w, a1.x, a1.y, a1.z, a1.w};
            float bv[8] = {b0.x, b0.y, b0.z, b0.w, b1.x, b1.y, b1.z, b1.w};
#pragma unroll
            for (int i = 0; i < 8; i++)
#pragma unroll
                for (int j = 0; j < 8; j++)
                    acc[i][j] = fmaf(av[i], bv[j], acc[i][j]);
        }
        __syncthreads();
    }

    // bias + relu
    float4 bb0 = *(const float4*)&bias[tx * 4];
    float4 bb1 = *(const float4*)&bias[64 + tx * 4];
    float bv[8] = {bb0.x, bb0.y, bb0.z, bb0.w, bb1.x, bb1.y, bb1.z, bb1.w};

    float colsum[8];
#pragma unroll
    for (int j = 0; j < 8; j++) colsum[j] = 0.0f;

#pragma unroll
    for (int i = 0; i < 8; i++) {
        int gr = bm + ((i < 4) ? (ty * 4 + i) : (64 + ty * 4 + (i - 4)));
        if (gr >= M) continue;
        float r[8];
#pragma unroll
        for (int j = 0; j < 8; j++) r[j] = fmaxf(acc[i][j] + bv[j], 0.0f);
        if (POOL) {
#pragma unroll
            for (int j = 0; j < 8; j++) colsum[j] += r[j];
        } else {
            __half2 h0 = __floats2half2_rn(r[0], r[1]);
            __half2 h1 = __floats2half2_rn(r[2], r[3]);
            __half2 h2 = __floats2half2_rn(r[4], r[5]);
            __half2 h3 = __floats2half2_rn(r[6], r[7]);
            uint2 w0, w1;
            w0.x = *reinterpret_cast<unsigned*>(&h0);
            w0.y = *reinterpret_cast<unsigned*>(&h1);
            w1.x = *reinterpret_cast<unsigned*>(&h2);
            w1.y = *reinterpret_cast<unsigned*>(&h3);
            *reinterpret_cast<uint2*>(&Out[(size_t)gr * F + tx * 4]) = w0;
            *reinterpret_cast<uint2*>(&Out[(size_t)gr * F + 64 + tx * 4]) = w1;
        }
    }

    if (POOL) {
        __syncthreads();   // spool init visible
#pragma unroll
        for (int j = 0; j < 4; j++) atomicAdd(&spool[tx * 4 + j], colsum[j]);
#pragma unroll
        for (int j = 0; j < 4; j++) atomicAdd(&spool[64 + tx * 4 + j], colsum[4 + j]);
        __syncthreads();
        if (tid < F) atomicAdd(&g_pool[tid], spool[tid]);
    }
}

// ---------------- FC ---------------------------------------------------------
__global__ void k_fc(const float* __restrict__ fw, const float* __restrict__ fb,
                     float* __restrict__ out) {
    int jj = threadIdx.x;
    if (jj < 2) {
        const float inv_n = 1.0f / (float)N_NODES;
        float s = 0.0f;
        for (int k = 0; k < F; k++)
            s += g_pool[k] * inv_n * fw[k * 2 + jj];
        out[jj] = s + fb[jj];
    }
}

// ---------------- launch -----------------------------------------------------
extern "C" void kernel_launch(void* const* d_in, const int* in_sizes, int n_in,
                              void* d_out, int out_size) {
    const float* x   = (const float*)d_in[0];
    const int*   ei  = (const int*)d_in[1];
    const float* W1  = (const float*)d_in[2];
    const float* b1  = (const float*)d_in[3];
    const float* W2  = (const float*)d_in[4];
    const float* b2  = (const float*)d_in[5];
    const float* W3  = (const float*)d_in[6];
    const float* b3  = (const float*)d_in[7];
    const float* fcw = (const float*)d_in[8];
    const float* fcb = (const float*)d_in[9];
    float* out = (float*)d_out;

    const int* e_src = ei;
    const int* e_dst = ei + N_EDGES;

    float* t;
    __half* f16;
    cudaGetSymbolAddress((void**)&t,   g_t);
    cudaGetSymbolAddress((void**)&f16, g_feat16);

    // ---- CSR build ----
    k_zero<<<(N_NODES + 255) / 256, 256>>>();
    k_hist<<<(N_EDGES + 255) / 256, 256>>>(e_dst);
    k_dinv<<<(N_NODES + 255) / 256, 256>>>();
    k_scanA<<<(NCHUNK * 32 + 255) / 256, 256>>>();
    k_scanB<<<1, 1024>>>();
    k_scanC<<<(NCHUNK * 32 + 255) / 256, 256>>>();
    k_fill<<<(N_EDGES + 255) / 256, 256>>>(e_src, e_dst);

    // ---- x -> fp16 ----
    k_cvt<<<(N_NODES * 32 + 255) / 256, 256>>>(x);

    const int gemm_grid = (N_NODES + 127) / 128;
    const int agg_grid  = (N_NODES + 7) / 8;

    // layer 1
    k_agg<<<agg_grid, 256>>>();
    k_gemm<false><<<gemm_grid, 256>>>(t, W1, b1, f16, N_NODES);
    // layer 2
    k_agg<<<agg_grid, 256>>>();
    k_gemm<false><<<gemm_grid, 256>>>(t, W2, b2, f16, N_NODES);
    // layer 3 (pool fused into GEMM epilogue; no feature write)
    k_agg<<<agg_grid, 256>>>();
    k_gemm<true><<<gemm_grid, 256>>>(t, W3, b3, f16, N_NODES);

    k_fc<<<1, 32>>>(fcw, fcb, out);
}

// round 14
// speedup vs baseline: 2.2457x; 1.0119x over previous
#include <cuda_runtime.h>
#include <cuda_fp16.h>
#include <mma.h>

#define N_NODES 100000
#define N_EDGES 1600000
#define F 128
#define CHUNK 128
#define NCHUNK ((N_NODES + CHUNK - 1) / CHUNK)   // 782

using namespace nvcuda;

// ---------------- scratch (device globals; no runtime allocation) ----------
__device__ int    g_cnt[N_NODES];       // degree count -> CSR cursor -> row end
__device__ int    g_rowptr[N_NODES];    // CSR row start
__device__ int    g_chunksums[1024];
__device__ int    g_esrc[N_EDGES];      // edge sources, grouped by dst
__device__ float  g_dinv[N_NODES];
__device__ __half g_feat16[(size_t)N_NODES * F];  // layer input features
__device__ __half g_t16[(size_t)N_NODES * F];     // aggregated features (GEMM A)
__device__ __half g_w16[3 * F * F];               // fp16 weights
__device__ float  g_pool[F];

// ---------------- init / degree ---------------------------------------------
__global__ void k_zero() {
    int i = blockIdx.x * blockDim.x + threadIdx.x;
    if (i < N_NODES) g_cnt[i] = 0;
    if (i < F) g_pool[i] = 0.0f;
}

__global__ void k_hist(const int* __restrict__ dst) {
    int e = blockIdx.x * blockDim.x + threadIdx.x;
    if (e < N_EDGES) atomicAdd(&g_cnt[dst[e]], 1);
}

__global__ void k_dinv() {
    int i = blockIdx.x * blockDim.x + threadIdx.x;
    if (i < N_NODES) g_dinv[i] = rsqrtf(1.0f + (float)g_cnt[i]);
}

// ---------------- CSR scan ---------------------------------------------------
__global__ void k_scanA() {
    int warp = (blockIdx.x * blockDim.x + threadIdx.x) >> 5;
    int lane = threadIdx.x & 31;
    if (warp >= NCHUNK) return;
    int base = warp * CHUNK + lane * 4;
    int s = 0;
#pragma unroll
    for (int j = 0; j < 4; j++) {
        int idx = base + j;
        if (idx < N_NODES) s += g_cnt[idx];
    }
#pragma unroll
    for (int off = 16; off > 0; off >>= 1)
        s += __shfl_down_sync(0xffffffffu, s, off);
    if (lane == 0) g_chunksums[warp] = s;
}

__global__ void k_scanB() {
    __shared__ int sh[1024];
    int t = threadIdx.x;
    int v = (t < NCHUNK) ? g_chunksums[t] : 0;
    sh[t] = v;
    __syncthreads();
    for (int off = 1; off < 1024; off <<= 1) {
        int x = sh[t];
        if (t >= off) x += sh[t - off];
        __syncthreads();
        sh[t] = x;
        __syncthreads();
    }
    if (t < NCHUNK) g_chunksums[t] = sh[t] - v;
}

__global__ void k_scanC() {
    int warp = (blockIdx.x * blockDim.x + threadIdx.x) >> 5;
    int lane = threadIdx.x & 31;
    if (warp >= NCHUNK) return;
    int base = warp * CHUNK + lane * 4;
    int v[4];
#pragma unroll
    for (int j = 0; j < 4; j++) {
        int idx = base + j;
        v[j] = (idx < N_NODES) ? g_cnt[idx] : 0;
    }
    int t1 = v[0], t2 = t1 + v[1], t3 = t2 + v[2], tot = t3 + v[3];
    int x = tot;
#pragma unroll
    for (int off = 1; off < 32; off <<= 1) {
        int y = __shfl_up_sync(0xffffffffu, x, off);
        if (lane >= off) x += y;
    }
    int b = g_chunksums[warp] + (x - tot);
    int pre[4] = {b, b + t1, b + t2, b + t3};
#pragma unroll
    for (int j = 0; j < 4; j++) {
        int idx = base + j;
        if (idx < N_NODES) { g_rowptr[idx] = pre[j]; g_cnt[idx] = pre[j]; }
    }
}

__global__ void k_fill(const int* __restrict__ src, const int* __restrict__ dst) {
    int e = blockIdx.x * blockDim.x + threadIdx.x;
    if (e >= N_EDGES) return;
    int d = __ldg(&dst[e]);
    int pos = atomicAdd(&g_cnt[d], 1);
    g_esrc[pos] = __ldg(&src[e]);
}

// ---------------- conversions ------------------------------------------------
__global__ void k_cvt(const float* __restrict__ x) {     // x -> g_feat16
    int idx = blockIdx.x * blockDim.x + threadIdx.x;
    if (idx >= N_NODES * 32) return;
    float4 v = *(const float4*)&x[(size_t)idx * 4];
    __half2 h0 = __floats2half2_rn(v.x, v.y);
    __half2 h1 = __floats2half2_rn(v.z, v.w);
    uint2 r;
    r.x = *reinterpret_cast<unsigned*>(&h0);
    r.y = *reinterpret_cast<unsigned*>(&h1);
    *reinterpret_cast<uint2*>(&g_feat16[(size_t)idx * 4]) = r;
}

__global__ void k_cvtW(const float* __restrict__ W, int slot) {
    int idx = blockIdx.x * blockDim.x + threadIdx.x;   // F*F/4
    if (idx >= F * F / 4) return;
    float4 v = *(const float4*)&W[(size_t)idx * 4];
    __half2 h0 = __floats2half2_rn(v.x, v.y);
    __half2 h1 = __floats2half2_rn(v.z, v.w);
    uint2 r;
    r.x = *reinterpret_cast<unsigned*>(&h0);
    r.y = *reinterpret_cast<unsigned*>(&h1);
    *reinterpret_cast<uint2*>(&g_w16[slot * F * F + idx * 4]) = r;
}

// ---------------- aggregation: t16 = Â * feat16 (fp32 accum, fp16 out) -------
__global__ void __launch_bounds__(256) k_agg() {
    const int warp = threadIdx.x >> 5;
    const int lane = threadIdx.x & 31;
    const int node = blockIdx.x * 8 + warp;
    if (node >= N_NODES) return;

    const __half* in16 = g_feat16;
    const float di = g_dinv[node];

    float4 acc;
    {
        uint2 r = __ldg((const uint2*)(in16 + (size_t)node * F + lane * 4));
        float2 f0 = __half22float2(*reinterpret_cast<__half2*>(&r.x));
        float2 f1 = __half22float2(*reinterpret_cast<__half2*>(&r.y));
        acc.x = di * f0.x; acc.y = di * f0.y;
        acc.z = di * f1.x; acc.w = di * f1.y;
    }

    int j   = g_rowptr[node];
    int end = g_cnt[node];
#pragma unroll 4
    for (; j < end; j++) {
        int s = __ldg(&g_esrc[j]);
        float w = __ldg(&g_dinv[s]);
        uint2 r = __ldg((const uint2*)(in16 + (size_t)s * F + lane * 4));
        float2 f0 = __half22float2(*reinterpret_cast<__half2*>(&r.x));
        float2 f1 = __half22float2(*reinterpret_cast<__half2*>(&r.y));
        acc.x = fmaf(w, f0.x, acc.x);
        acc.y = fmaf(w, f0.y, acc.y);
        acc.z = fmaf(w, f1.x, acc.z);
        acc.w = fmaf(w, f1.y, acc.w);
    }
    __half2 h0 = __floats2half2_rn(acc.x * di, acc.y * di);
    __half2 h1 = __floats2half2_rn(acc.z * di, acc.w * di);
    uint2 r;
    r.x = *reinterpret_cast<unsigned*>(&h0);
    r.y = *reinterpret_cast<unsigned*>(&h1);
    *reinterpret_cast<uint2*>(&g_t16[(size_t)node * F + lane * 4]) = r;
}

// ---------------- WMMA GEMM: relu(A16[M,128] @ W16[128,128] + b) -------------
// 64x128 block tile, 8 warps (4 on M x 2 on N), warp tile 16x64.
// sA 16KB + sW 32KB = 48KB static; sW reused as fp32 C tile after mainloop.
__global__ void __launch_bounds__(256) k_hgemm_store(const __half* __restrict__ A,
                                                     const __half* __restrict__ Wh,
                                                     const float* __restrict__ bias,
                                                     __half* __restrict__ Out, int M) {
    __shared__ __half sA[64 * F];     // 16 KB
    __shared__ __half sW[F * F];      // 32 KB, reused as C (64x128 fp32)

    const int tid = threadIdx.x;
    const int bm  = blockIdx.x * 64;

    // stage A (64x128, zero-fill OOB): 1024 16B chunks, 4/thread
    for (int it = 0; it < 4; it++) {
        int idx = tid + it * 256;
        int r   = idx >> 4;
        int c8  = idx & 15;
        uint4 v = make_uint4(0, 0, 0, 0);
        int gr = bm + r;
        if (gr < M) v = *(const uint4*)&A[(size_t)gr * F + c8 * 8];
        *(uint4*)&sA[r * F + c8 * 8] = v;
    }
    // stage W (128x128): 2048 chunks, 8/thread
    for (int it = 0; it < 8; it++) {
        int idx = tid + it * 256;
        int r   = idx >> 4;
        int c8  = idx & 15;
        *(uint4*)&sW[r * F + c8 * 8] = *(const uint4*)&Wh[r * F + c8 * 8];
    }
    __syncthreads();

    const int warp = tid >> 5;
    const int wm = (warp & 3) * 16;        // 0,16,32,48
    const int wn = (warp >> 2) * 64;       // 0,64

    wmma::fragment<wmma::accumulator, 16, 16, 16, float> c0, c1, c2, c3;
    wmma::fill_fragment(c0, 0.0f);
    wmma::fill_fragment(c1, 0.0f);
    wmma::fill_fragment(c2, 0.0f);
    wmma::fill_fragment(c3, 0.0f);

    for (int k0 = 0; k0 < F; k0 += 16) {
        wmma::fragment<wmma::matrix_a, 16, 16, 16, __half, wmma::row_major> a;
        wmma::load_matrix_sync(a, &sA[wm * F + k0], F);
        wmma::fragment<wmma::matrix_b, 16, 16, 16, __half, wmma::row_major> b;
        wmma::load_matrix_sync(b, &sW[k0 * F + wn], F);
        wmma::mma_sync(c0, a, b, c0);
        wmma::load_matrix_sync(b, &sW[k0 * F + wn + 16], F);
        wmma::mma_sync(c1, a, b, c1);
        wmma::load_matrix_sync(b, &sW[k0 * F + wn + 32], F);
        wmma::mma_sync(c2, a, b, c2);
        wmma::load_matrix_sync(b, &sW[k0 * F + wn + 48], F);
        wmma::mma_sync(c3, a, b, c3);
    }

    __syncthreads();                       // done reading sW
    float* sC = reinterpret_cast<float*>(sW);   // 64x128 fp32
    wmma::store_matrix_sync(&sC[wm * F + wn],      c0, F, wmma::mem_row_major);
    wmma::store_matrix_sync(&sC[wm * F + wn + 16], c1, F, wmma::mem_row_major);
    wmma::store_matrix_sync(&sC[wm * F + wn + 32], c2, F, wmma::mem_row_major);
    wmma::store_matrix_sync(&sC[wm * F + wn + 48], c3, F, wmma::mem_row_major);
    __syncthreads();

    // epilogue: bias + relu + fp16 store. 64*32 float4 units, 8/thread.
    for (int it = 0; it < 8; it++) {
        int idx = tid + it * 256;
        int row = idx >> 5;
        int c4  = idx & 31;
        int gr  = bm + row;
        if (gr < M) {
            float4 v  = *(float4*)&sC[row * F + c4 * 4];
            float4 bb = *(const float4*)&bias[c4 * 4];
            __half2 h0 = __floats2half2_rn(fmaxf(v.x + bb.x, 0.0f),
                                           fmaxf(v.y + bb.y, 0.0f));
            __half2 h1 = __floats2half2_rn(fmaxf(v.z + bb.z, 0.0f),
                                           fmaxf(v.w + bb.w, 0.0f));
            uint2 r;
            r.x = *reinterpret_cast<unsigned*>(&h0);
            r.y = *reinterpret_cast<unsigned*>(&h1);
            *reinterpret_cast<uint2*>(&Out[(size_t)gr * F + c4 * 4]) = r;
        }
    }
}

__global__ void __launch_bounds__(256) k_hgemm_pool(const __half* __restrict__ A,
                                                    const __half* __restrict__ Wh,
                                                    const float* __restrict__ bias,
                                                    int M) {
    __shared__ __half sA[64 * F];     // 16 KB, reused as pool scratch
    __shared__ __half sW[F * F];      // 32 KB, reused as C

    const int tid = threadIdx.x;
    const int bm  = blockIdx.x * 64;

    for (int it = 0; it < 4; it++) {
        int idx = tid + it * 256;
        int r   = idx >> 4;
        int c8  = idx & 15;
        uint4 v = make_uint4(0, 0, 0, 0);
        int gr = bm + r;
        if (gr < M) v = *(const uint4*)&A[(size_t)gr * F + c8 * 8];
        *(uint4*)&sA[r * F + c8 * 8] = v;
    }
    for (int it = 0; it < 8; it++) {
        int idx = tid + it * 256;
        int r   = idx >> 4;
        int c8  = idx & 15;
        *(uint4*)&sW[r * F + c8 * 8] = *(const uint4*)&Wh[r * F + c8 * 8];
    }
    __syncthreads();

    const int warp = tid >> 5;
    const int wm = (warp & 3) * 16;
    const int wn = (warp >> 2) * 64;

    wmma::fragment<wmma::accumulator, 16, 16, 16, float> c0, c1, c2, c3;
    wmma::fill_fragment(c0, 0.0f);
    wmma::fill_fragment(c1, 0.0f);
    wmma::fill_fragment(c2, 0.0f);
    wmma::fill_fragment(c3, 0.0f);

    for (int k0 = 0; k0 < F; k0 += 16) {
        wmma::fragment<wmma::matrix_a, 16, 16, 16, __half, wmma::row_major> a;
        wmma::load_matrix_sync(a, &sA[wm * F + k0], F);
        wmma::fragment<wmma::matrix_b, 16, 16, 16, __half, wmma::row_major> b;
        wmma::load_matrix_sync(b, &sW[k0 * F + wn], F);
        wmma::mma_sync(c0, a, b, c0);
        wmma::load_matrix_sync(b, &sW[k0 * F + wn + 16], F);
        wmma::mma_sync(c1, a, b, c1);
        wmma::load_matrix_sync(b, &sW[k0 * F + wn + 32], F);
        wmma::mma_sync(c2, a, b, c2);
        wmma::load_matrix_sync(b, &sW[k0 * F + wn + 48], F);
        wmma::mma_sync(c3, a, b, c3);
    }

    __syncthreads();
    float* sC = reinterpret_cast<float*>(sW);
    wmma::store_matrix_sync(&sC[wm * F + wn],      c0, F, wmma::mem_row_major);
    wmma::store_matrix_sync(&sC[wm * F + wn + 16], c1, F, wmma::mem_row_major);
    wmma::store_matrix_sync(&sC[wm * F + wn + 32], c2, F, wmma::mem_row_major);
    wmma::store_matrix_sync(&sC[wm * F + wn + 48], c3, F, wmma::mem_row_major);
    __syncthreads();

    // epilogue: bias + relu + column-sum into g_pool (exclude OOB rows)
    int rowmax = M - bm;
    if (rowmax > 64) rowmax = 64;
    if (tid < F) {
        float bb = bias[tid];
        float s = 0.0f;
        for (int row = 0; row < rowmax; row++)
            s += fmaxf(sC[row * F + tid] + bb, 0.0f);
        atomicAdd(&g_pool[tid], s);
    }
}

// ---------------- FC ---------------------------------------------------------
__global__ void k_fc(const float* __restrict__ fw, const float* __restrict__ fb,
                     float* __restrict__ out) {
    int jj = threadIdx.x;
    if (jj < 2) {
        const float inv_n = 1.0f / (float)N_NODES;
        float s = 0.0f;
        for (int k = 0; k < F; k++)
            s += g_pool[k] * inv_n * fw[k * 2 + jj];
        out[jj] = s + fb[jj];
    }
}

// ---------------- launch -----------------------------------------------------
extern "C" void kernel_launch(void* const* d_in, const int* in_sizes, int n_in,
                              void* d_out, int out_size) {
    const float* x   = (const float*)d_in[0];
    const int*   ei  = (const int*)d_in[1];
    const float* W1  = (const float*)d_in[2];
    const float* b1  = (const float*)d_in[3];
    const float* W2  = (const float*)d_in[4];
    const float* b2  = (const float*)d_in[5];
    const float* W3  = (const float*)d_in[6];
    const float* b3  = (const float*)d_in[7];
    const float* fcw = (const float*)d_in[8];
    const float* fcb = (const float*)d_in[9];
    float* out = (float*)d_out;

    const int* e_src = ei;
    const int* e_dst = ei + N_EDGES;

    __half *t16, *f16, *w16;
    cudaGetSymbolAddress((void**)&t16, g_t16);
    cudaGetSymbolAddress((void**)&f16, g_feat16);
    cudaGetSymbolAddress((void**)&w16, g_w16);

    // ---- CSR build ----
    k_zero<<<(N_NODES + 255) / 256, 256>>>();
    k_hist<<<(N_EDGES + 255) / 256, 256>>>(e_dst);
    k_dinv<<<(N_NODES + 255) / 256, 256>>>();
    k_scanA<<<(NCHUNK * 32 + 255) / 256, 256>>>();
    k_scanB<<<1, 1024>>>();
    k_scanC<<<(NCHUNK * 32 + 255) / 256, 256>>>();
    k_fill<<<(N_EDGES + 255) / 256, 256>>>(e_src, e_dst);

    // ---- conversions ----
    k_cvt<<<(N_NODES * 32 + 255) / 256, 256>>>(x);
    k_cvtW<<<(F * F / 4 + 255) / 256, 256>>>(W1, 0);
    k_cvtW<<<(F * F / 4 + 255) / 256, 256>>>(W2, 1);
    k_cvtW<<<(F * F / 4 + 255) / 256, 256>>>(W3, 2);

    const int gemm_grid = (N_NODES + 63) / 64;
    const int agg_grid  = (N_NODES + 7) / 8;

    // layer 1
    k_agg<<<agg_grid, 256>>>();
    k_hgemm_store<<<gemm_grid, 256>>>(t16, w16 + 0 * F * F, b1, f16, N_NODES);
    // layer 2
    k_agg<<<agg_grid, 256>>>();
    k_hgemm_store<<<gemm_grid, 256>>>(t16, w16 + 1 * F * F, b2, f16, N_NODES);
    // layer 3 (pool fused into epilogue)
    k_agg<<<agg_grid, 256>>>();
    k_hgemm_pool<<<gemm_grid, 256>>>(t16, w16 + 2 * F * F, b3, N_NODES);

    k_fc<<<1, 32>>>(fcw, fcb, out);
}

// round 16
// speedup vs baseline: 3.4649x; 1.5429x over previous
#include <cuda_runtime.h>
#include <cuda_fp16.h>
#include <mma.h>

#define N_NODES 100000
#define N_EDGES 1600000
#define F 128
#define CHUNK 128
#define NCHUNK ((N_NODES + CHUNK - 1) / CHUNK)   // 782
#define LDH 136    // padded half stride (272 B: 4-bank rotate per row)
#define LDC 132    // padded float stride (528 B: 4-bank rotate per row)

using namespace nvcuda;

// ---------------- scratch (device globals; no runtime allocation) ----------
__device__ int    g_cnt[N_NODES];       // degree count -> CSR cursor -> row end
__device__ int    g_rowptr[N_NODES];    // CSR row start
__device__ int    g_chunksums[1024];
__device__ int    g_esrc[N_EDGES];      // edge sources, grouped by dst
__device__ float  g_dinv[N_NODES];
__device__ __half g_feat16[(size_t)N_NODES * F];  // layer input features
__device__ __half g_t16[(size_t)N_NODES * F];     // aggregated features (GEMM A)
__device__ __half g_w16[3 * F * F];               // fp16 weights
__device__ float  g_pool[F];

// ---------------- init / degree ---------------------------------------------
__global__ void k_zero() {
    int i = blockIdx.x * blockDim.x + threadIdx.x;
    if (i < N_NODES) g_cnt[i] = 0;
    if (i < F) g_pool[i] = 0.0f;
}

__global__ void k_hist(const int* __restrict__ dst) {
    int e = blockIdx.x * blockDim.x + threadIdx.x;
    if (e < N_EDGES) atomicAdd(&g_cnt[dst[e]], 1);
}

__global__ void k_dinv() {
    int i = blockIdx.x * blockDim.x + threadIdx.x;
    if (i < N_NODES) g_dinv[i] = rsqrtf(1.0f + (float)g_cnt[i]);
}

// ---------------- CSR scan ---------------------------------------------------
__global__ void k_scanA() {
    int warp = (blockIdx.x * blockDim.x + threadIdx.x) >> 5;
    int lane = threadIdx.x & 31;
    if (warp >= NCHUNK) return;
    int base = warp * CHUNK + lane * 4;
    int s = 0;
#pragma unroll
    for (int j = 0; j < 4; j++) {
        int idx = base + j;
        if (idx < N_NODES) s += g_cnt[idx];
    }
#pragma unroll
    for (int off = 16; off > 0; off >>= 1)
        s += __shfl_down_sync(0xffffffffu, s, off);
    if (lane == 0) g_chunksums[warp] = s;
}

__global__ void k_scanB() {
    __shared__ int sh[1024];
    int t = threadIdx.x;
    int v = (t < NCHUNK) ? g_chunksums[t] : 0;
    sh[t] = v;
    __syncthreads();
    for (int off = 1; off < 1024; off <<= 1) {
        int x = sh[t];
        if (t >= off) x += sh[t - off];
        __syncthreads();
        sh[t] = x;
        __syncthreads();
    }
    if (t < NCHUNK) g_chunksums[t] = sh[t] - v;
}

__global__ void k_scanC() {
    int warp = (blockIdx.x * blockDim.x + threadIdx.x) >> 5;
    int lane = threadIdx.x & 31;
    if (warp >= NCHUNK) return;
    int base = warp * CHUNK + lane * 4;
    int v[4];
#pragma unroll
    for (int j = 0; j < 4; j++) {
        int idx = base + j;
        v[j] = (idx < N_NODES) ? g_cnt[idx] : 0;
    }
    int t1 = v[0], t2 = t1 + v[1], t3 = t2 + v[2], tot = t3 + v[3];
    int x = tot;
#pragma unroll
    for (int off = 1; off < 32; off <<= 1) {
        int y = __shfl_up_sync(0xffffffffu, x, off);
        if (lane >= off) x += y;
    }
    int b = g_chunksums[warp] + (x - tot);
    int pre[4] = {b, b + t1, b + t2, b + t3};
#pragma unroll
    for (int j = 0; j < 4; j++) {
        int idx = base + j;
        if (idx < N_NODES) { g_rowptr[idx] = pre[j]; g_cnt[idx] = pre[j]; }
    }
}

__global__ void k_fill(const int* __restrict__ src, const int* __restrict__ dst) {
    int e = blockIdx.x * blockDim.x + threadIdx.x;
    if (e >= N_EDGES) return;
    int d = __ldg(&dst[e]);
    int pos = atomicAdd(&g_cnt[d], 1);
    g_esrc[pos] = __ldg(&src[e]);
}

// ---------------- conversions ------------------------------------------------
__global__ void k_cvt(const float* __restrict__ x) {     // x -> g_feat16
    int idx = blockIdx.x * blockDim.x + threadIdx.x;
    if (idx >= N_NODES * 32) return;
    float4 v = *(const float4*)&x[(size_t)idx * 4];
    __half2 h0 = __floats2half2_rn(v.x, v.y);
    __half2 h1 = __floats2half2_rn(v.z, v.w);
    uint2 r;
    r.x = *reinterpret_cast<unsigned*>(&h0);
    r.y = *reinterpret_cast<unsigned*>(&h1);
    *reinterpret_cast<uint2*>(&g_feat16[(size_t)idx * 4]) = r;
}

__global__ void k_cvtW(const float* __restrict__ W, int slot) {
    int idx = blockIdx.x * blockDim.x + threadIdx.x;   // F*F/4
    if (idx >= F * F / 4) return;
    float4 v = *(const float4*)&W[(size_t)idx * 4];
    __half2 h0 = __floats2half2_rn(v.x, v.y);
    __half2 h1 = __floats2half2_rn(v.z, v.w);
    uint2 r;
    r.x = *reinterpret_cast<unsigned*>(&h0);
    r.y = *reinterpret_cast<unsigned*>(&h1);
    *reinterpret_cast<uint2*>(&g_w16[slot * F * F + idx * 4]) = r;
}

// ---------------- aggregation: t16 = Â * feat16 (fp32 accum, fp16 out) -------
__global__ void __launch_bounds__(256) k_agg() {
    const int warp = threadIdx.x >> 5;
    const int lane = threadIdx.x & 31;
    const int node = blockIdx.x * 8 + warp;
    if (node >= N_NODES) return;

    const __half* in16 = g_feat16;
    const float di = g_dinv[node];

    float4 acc;
    {
        uint2 r = __ldg((const uint2*)(in16 + (size_t)node * F + lane * 4));
        float2 f0 = __half22float2(*reinterpret_cast<__half2*>(&r.x));
        float2 f1 = __half22float2(*reinterpret_cast<__half2*>(&r.y));
        acc.x = di * f0.x; acc.y = di * f0.y;
        acc.z = di * f1.x; acc.w = di * f1.y;
    }

    int j   = g_rowptr[node];
    int end = g_cnt[node];
#pragma unroll 4
    for (; j < end; j++) {
        int s = __ldg(&g_esrc[j]);
        float w = __ldg(&g_dinv[s]);
        uint2 r = __ldg((const uint2*)(in16 + (size_t)s * F + lane * 4));
        float2 f0 = __half22float2(*reinterpret_cast<__half2*>(&r.x));
        float2 f1 = __half22float2(*reinterpret_cast<__half2*>(&r.y));
        acc.x = fmaf(w, f0.x, acc.x);
        acc.y = fmaf(w, f0.y, acc.y);
        acc.z = fmaf(w, f1.x, acc.z);
        acc.w = fmaf(w, f1.y, acc.w);
    }
    __half2 h0 = __floats2half2_rn(acc.x * di, acc.y * di);
    __half2 h1 = __floats2half2_rn(acc.z * di, acc.w * di);
    uint2 r;
    r.x = *reinterpret_cast<unsigned*>(&h0);
    r.y = *reinterpret_cast<unsigned*>(&h1);
    *reinterpret_cast<uint2*>(&g_t16[(size_t)node * F + lane * 4]) = r;
}

// ---------------- WMMA GEMM: relu(A16[M,128] @ W16[128,128] + b) -------------
// 32x128 block tile, 8 warps (2 on M x 4 on N), warp tile 16x32.
// Padded smem rows (LDH=136 halves / LDC=132 floats) -> conflict-free ldsm/C.
__global__ void __launch_bounds__(256) k_hgemm_store(const __half* __restrict__ A,
                                                     const __half* __restrict__ Wh,
                                                     const float* __restrict__ bias,
                                                     __half* __restrict__ Out, int M) {
    __shared__ __half sA[32 * LDH];   //  8.7 KB
    __shared__ __half sW[F * LDH];    // 34.8 KB, reused as C (32 x LDC fp32)

    const int tid = threadIdx.x;
    const int bm  = blockIdx.x * 32;

    // stage A (32x128, zero-fill OOB): 512 16B chunks, 2/thread
    for (int it = 0; it < 2; it++) {
        int idx = tid + it * 256;
        int r   = idx >> 4;
        int c8  = idx & 15;
        uint4 v = make_uint4(0, 0, 0, 0);
        int gr = bm + r;
        if (gr < M) v = *(const uint4*)&A[(size_t)gr * F + c8 * 8];
        *(uint4*)&sA[r * LDH + c8 * 8] = v;
    }
    // stage W (128x128): 2048 chunks, 8/thread
    for (int it = 0; it < 8; it++) {
        int idx = tid + it * 256;
        int r   = idx >> 4;
        int c8  = idx & 15;
        *(uint4*)&sW[r * LDH + c8 * 8] = *(const uint4*)&Wh[r * F + c8 * 8];
    }
    __syncthreads();

    const int warp = tid >> 5;
    const int wm = (warp & 1) * 16;        // 0,16
    const int wn = (warp >> 1) * 32;       // 0,32,64,96

    wmma::fragment<wmma::accumulator, 16, 16, 16, float> c0, c1;
    wmma::fill_fragment(c0, 0.0f);
    wmma::fill_fragment(c1, 0.0f);

    for (int k0 = 0; k0 < F; k0 += 16) {
        wmma::fragment<wmma::matrix_a, 16, 16, 16, __half, wmma::row_major> a;
        wmma::load_matrix_sync(a, &sA[wm * LDH + k0], LDH);
        wmma::fragment<wmma::matrix_b, 16, 16, 16, __half, wmma::row_major> b;
        wmma::load_matrix_sync(b, &sW[k0 * LDH + wn], LDH);
        wmma::mma_sync(c0, a, b, c0);
        wmma::load_matrix_sync(b, &sW[k0 * LDH + wn + 16], LDH);
        wmma::mma_sync(c1, a, b, c1);
    }

    __syncthreads();                       // done reading sW
    float* sC = reinterpret_cast<float*>(sW);   // 32 x LDC fp32
    wmma::store_matrix_sync(&sC[wm * LDC + wn],      c0, LDC, wmma::mem_row_major);
    wmma::store_matrix_sync(&sC[wm * LDC + wn + 16], c1, LDC, wmma::mem_row_major);
    __syncthreads();

    // epilogue: bias + relu + fp16 store. 32*32 float4 units, 4/thread.
    for (int it = 0; it < 4; it++) {
        int idx = tid + it * 256;
        int row = idx >> 5;
        int c4  = idx & 31;
        int gr  = bm + row;
        if (gr < M) {
            float4 v  = *(float4*)&sC[row * LDC + c4 * 4];
            float4 bb = *(const float4*)&bias[c4 * 4];
            __half2 h0 = __floats2half2_rn(fmaxf(v.x + bb.x, 0.0f),
                                           fmaxf(v.y + bb.y, 0.0f));
            __half2 h1 = __floats2half2_rn(fmaxf(v.z + bb.z, 0.0f),
                                           fmaxf(v.w + bb.w, 0.0f));
            uint2 r;
            r.x = *reinterpret_cast<unsigned*>(&h0);
            r.y = *reinterpret_cast<unsigned*>(&h1);
            *reinterpret_cast<uint2*>(&Out[(size_t)gr * F + c4 * 4]) = r;
        }
    }
}

__global__ void __launch_bounds__(256) k_hgemm_pool(const __half* __restrict__ A,
                                                    const __half* __restrict__ Wh,
                                                    const float* __restrict__ bias,
                                                    int M) {
    __shared__ __half sA[32 * LDH];
    __shared__ __half sW[F * LDH];    // reused as C

    const int tid = threadIdx.x;
    const int bm  = blockIdx.x * 32;

    for (int it = 0; it < 2; it++) {
        int idx = tid + it * 256;
        int r   = idx >> 4;
        int c8  = idx & 15;
        uint4 v = make_uint4(0, 0, 0, 0);
        int gr = bm + r;
        if (gr < M) v = *(const uint4*)&A[(size_t)gr * F + c8 * 8];
        *(uint4*)&sA[r * LDH + c8 * 8] = v;
    }
    for (int it = 0; it < 8; it++) {
        int idx = tid + it * 256;
        int r   = idx >> 4;
        int c8  = idx & 15;
        *(uint4*)&sW[r * LDH + c8 * 8] = *(const uint4*)&Wh[r * F + c8 * 8];
    }
    __syncthreads();

    const int warp = tid >> 5;
    const int wm = (warp & 1) * 16;
    const int wn = (warp >> 1) * 32;

    wmma::fragment<wmma::accumulator, 16, 16, 16, float> c0, c1;
    wmma::fill_fragment(c0, 0.0f);
    wmma::fill_fragment(c1, 0.0f);

    for (int k0 = 0; k0 < F; k0 += 16) {
        wmma::fragment<wmma::matrix_a, 16, 16, 16, __half, wmma::row_major> a;
        wmma::load_matrix_sync(a, &sA[wm * LDH + k0], LDH);
        wmma::fragment<wmma::matrix_b, 16, 16, 16, __half, wmma::row_major> b;
        wmma::load_matrix_sync(b, &sW[k0 * LDH + wn], LDH);
        wmma::mma_sync(c0, a, b, c0);
        wmma::load_matrix_sync(b, &sW[k0 * LDH + wn + 16], LDH);
        wmma::mma_sync(c1, a, b, c1);
    }

    __syncthreads();
    float* sC = reinterpret_cast<float*>(sW);
    wmma::store_matrix_sync(&sC[wm * LDC + wn],      c0, LDC, wmma::mem_row_major);
    wmma::store_matrix_sync(&sC[wm * LDC + wn + 16], c1, LDC, wmma::mem_row_major);
    __syncthreads();

    // epilogue: bias + relu + column-sum into g_pool (exclude OOB rows)
    int rowmax = M - bm;
    if (rowmax > 32) rowmax = 32;
    if (tid < F) {
        float bb = bias[tid];
        float s = 0.0f;
        for (int row = 0; row < rowmax; row++)
            s += fmaxf(sC[row * LDC + tid] + bb, 0.0f);
        atomicAdd(&g_pool[tid], s);
    }
}

// ---------------- FC ---------------------------------------------------------
__global__ void k_fc(const float* __restrict__ fw, const float* __restrict__ fb,
                     float* __restrict__ out) {
    int jj = threadIdx.x;
    if (jj < 2) {
        const float inv_n = 1.0f / (float)N_NODES;
        float s = 0.0f;
        for (int k = 0; k < F; k++)
            s += g_pool[k] * inv_n * fw[k * 2 + jj];
        out[jj] = s + fb[jj];
    }
}

// ---------------- launch -----------------------------------------------------
extern "C" void kernel_launch(void* const* d_in, const int* in_sizes, int n_in,
                              void* d_out, int out_size) {
    const float* x   = (const float*)d_in[0];
    const int*   ei  = (const int*)d_in[1];
    const float* W1  = (const float*)d_in[2];
    const float* b1  = (const float*)d_in[3];
    const float* W2  = (const float*)d_in[4];
    const float* b2  = (const float*)d_in[5];
    const float* W3  = (const float*)d_in[6];
    const float* b3  = (const float*)d_in[7];
    const float* fcw = (const float*)d_in[8];
    const float* fcb = (const float*)d_in[9];
    float* out = (float*)d_out;

    const int* e_src = ei;
    const int* e_dst = ei + N_EDGES;

    __half *t16, *f16, *w16;
    cudaGetSymbolAddress((void**)&t16, g_t16);
    cudaGetSymbolAddress((void**)&f16, g_feat16);
    cudaGetSymbolAddress((void**)&w16, g_w16);

    // ---- CSR build ----
    k_zero<<<(N_NODES + 255) / 256, 256>>>();
    k_hist<<<(N_EDGES + 255) / 256, 256>>>(e_dst);
    k_dinv<<<(N_NODES + 255) / 256, 256>>>();
    k_scanA<<<(NCHUNK * 32 + 255) / 256, 256>>>();
    k_scanB<<<1, 1024>>>();
    k_scanC<<<(NCHUNK * 32 + 255) / 256, 256>>>();
    k_fill<<<(N_EDGES + 255) / 256, 256>>>(e_src, e_dst);

    // ---- conversions ----
    k_cvt<<<(N_NODES * 32 + 255) / 256, 256>>>(x);
    k_cvtW<<<(F * F / 4 + 255) / 256, 256>>>(W1, 0);
    k_cvtW<<<(F * F / 4 + 255) / 256, 256>>>(W2, 1);
    k_cvtW<<<(F * F / 4 + 255) / 256, 256>>>(W3, 2);

    const int gemm_grid = (N_NODES + 31) / 32;
    const int agg_grid  = (N_NODES + 7) / 8;

    // layer 1
    k_agg<<<agg_grid, 256>>>();
    k_hgemm_store<<<gemm_grid, 256>>>(t16, w16 + 0 * F * F, b1, f16, N_NODES);
    // layer 2
    k_agg<<<agg_grid, 256>>>();
    k_hgemm_store<<<gemm_grid, 256>>>(t16, w16 + 1 * F * F, b2, f16, N_NODES);
    // layer 3 (pool fused into epilogue)
    k_agg<<<agg_grid, 256>>>();
    k_hgemm_pool<<<gemm_grid, 256>>>(t16, w16 + 2 * F * F, b3, N_NODES);

    k_fc<<<1, 32>>>(fcw, fcb, out);
}

// round 17
// speedup vs baseline: 3.7447x; 1.0808x over previous
#include <cuda_runtime.h>
#include <cuda_fp16.h>
#include <mma.h>

#define N_NODES 100000
#define N_EDGES 1600000
#define F 128
#define CHUNK 128
#define NCHUNK ((N_NODES + CHUNK - 1) / CHUNK)   // 782
#define LDH 136    // padded half stride (272 B: 4-bank rotate per row)
#define LDC 132    // padded float stride (528 B: 4-bank rotate per row)

using namespace nvcuda;

// ---------------- scratch (device globals; no runtime allocation) ----------
__device__ int    g_cnt[N_NODES];       // degree count -> CSR cursor -> row end
__device__ int    g_rowptr[N_NODES];    // CSR row start
__device__ int    g_chunksums[1024];
__device__ int2   g_edge[N_EDGES];      // packed {src, dinv[src] bits}, grouped by dst
__device__ float  g_dinv[N_NODES];
__device__ __half g_feat16[(size_t)N_NODES * F];  // layer input features
__device__ __half g_t16[(size_t)N_NODES * F];     // aggregated features (GEMM A)
__device__ __half g_w16[3 * F * F];               // fp16 weights
__device__ float  g_pool[F];

// ---------------- x -> fp16, plus zero-init (fused) --------------------------
__global__ void k_cvt(const float* __restrict__ x) {
    int idx = blockIdx.x * blockDim.x + threadIdx.x;
    if (idx < N_NODES) g_cnt[idx] = 0;
    if (idx < F) g_pool[idx] = 0.0f;
    if (idx >= N_NODES * 32) return;
    float4 v = *(const float4*)&x[(size_t)idx * 4];
    __half2 h0 = __floats2half2_rn(v.x, v.y);
    __half2 h1 = __floats2half2_rn(v.z, v.w);
    uint2 r;
    r.x = *reinterpret_cast<unsigned*>(&h0);
    r.y = *reinterpret_cast<unsigned*>(&h1);
    *reinterpret_cast<uint2*>(&g_feat16[(size_t)idx * 4]) = r;
}

__global__ void k_hist(const int* __restrict__ dst) {
    int e = blockIdx.x * blockDim.x + threadIdx.x;
    if (e < N_EDGES) atomicAdd(&g_cnt[dst[e]], 1);
}

// ---------------- CSR scan (dinv fused into phase A) -------------------------
__global__ void k_scanA() {
    int warp = (blockIdx.x * blockDim.x + threadIdx.x) >> 5;
    int lane = threadIdx.x & 31;
    if (warp >= NCHUNK) return;
    int base = warp * CHUNK + lane * 4;
    int s = 0;
#pragma unroll
    for (int j = 0; j < 4; j++) {
        int idx = base + j;
        if (idx < N_NODES) {
            int c = g_cnt[idx];
            s += c;
            g_dinv[idx] = rsqrtf(1.0f + (float)c);   // +1 self-loop
        }
    }
#pragma unroll
    for (int off = 16; off > 0; off >>= 1)
        s += __shfl_down_sync(0xffffffffu, s, off);
    if (lane == 0) g_chunksums[warp] = s;
}

__global__ void k_scanB() {
    __shared__ int sh[1024];
    int t = threadIdx.x;
    int v = (t < NCHUNK) ? g_chunksums[t] : 0;
    sh[t] = v;
    __syncthreads();
    for (int off = 1; off < 1024; off <<= 1) {
        int x = sh[t];
        if (t >= off) x += sh[t - off];
        __syncthreads();
        sh[t] = x;
        __syncthreads();
    }
    if (t < NCHUNK) g_chunksums[t] = sh[t] - v;
}

__global__ void k_scanC() {
    int warp = (blockIdx.x * blockDim.x + threadIdx.x) >> 5;
    int lane = threadIdx.x & 31;
    if (warp >= NCHUNK) return;
    int base = warp * CHUNK + lane * 4;
    int v[4];
#pragma unroll
    for (int j = 0; j < 4; j++) {
        int idx = base + j;
        v[j] = (idx < N_NODES) ? g_cnt[idx] : 0;
    }
    int t1 = v[0], t2 = t1 + v[1], t3 = t2 + v[2], tot = t3 + v[3];
    int x = tot;
#pragma unroll
    for (int off = 1; off < 32; off <<= 1) {
        int y = __shfl_up_sync(0xffffffffu, x, off);
        if (lane >= off) x += y;
    }
    int b = g_chunksums[warp] + (x - tot);
    int pre[4] = {b, b + t1, b + t2, b + t3};
#pragma unroll
    for (int j = 0; j < 4; j++) {
        int idx = base + j;
        if (idx < N_NODES) { g_rowptr[idx] = pre[j]; g_cnt[idx] = pre[j]; }
    }
}

// fill packed edge records {src, dinv[src]} (dinv gather paid once, not per layer)
__global__ void k_fill(const int* __restrict__ src, const int* __restrict__ dst) {
    int e = blockIdx.x * blockDim.x + threadIdx.x;
    if (e >= N_EDGES) return;
    int s = __ldg(&src[e]);
    int d = __ldg(&dst[e]);
    int pos = atomicAdd(&g_cnt[d], 1);
    int2 rec;
    rec.x = s;
    rec.y = __float_as_int(__ldg(&g_dinv[s]));
    g_edge[pos] = rec;
}

// ---------------- weights -> fp16 (all three in one kernel) ------------------
__global__ void k_cvtW3(const float* __restrict__ W1, const float* __restrict__ W2,
                        const float* __restrict__ W3) {
    int idx = blockIdx.x * blockDim.x + threadIdx.x;   // 3 * F*F/4
    if (idx >= 3 * F * F / 4) return;
    int slot = idx / (F * F / 4);
    int off  = idx % (F * F / 4);
    const float* W = (slot == 0) ? W1 : (slot == 1) ? W2 : W3;
    float4 v = *(const float4*)&W[(size_t)off * 4];
    __half2 h0 = __floats2half2_rn(v.x, v.y);
    __half2 h1 = __floats2half2_rn(v.z, v.w);
    uint2 r;
    r.x = *reinterpret_cast<unsigned*>(&h0);
    r.y = *reinterpret_cast<unsigned*>(&h1);
    *reinterpret_cast<uint2*>(&g_w16[slot * F * F + off * 4]) = r;
}

// ---------------- aggregation: t16 = Â * feat16 ------------------------------
// warp per node. Edge records prefetched lane-parallel into smem; feature
// gathers then issue with no index dependency, manually 4-wide unrolled.
__global__ void __launch_bounds__(256) k_agg() {
    __shared__ int   sSrc[8][32];
    __shared__ float sWt[8][32];
    const int warp = threadIdx.x >> 5;
    const int lane = threadIdx.x & 31;
    const int node = blockIdx.x * 8 + warp;
    if (node >= N_NODES) return;

    const __half* in16 = g_feat16;
    const float di = g_dinv[node];

    float4 acc;
    {
        uint2 r = __ldg((const uint2*)(in16 + (size_t)node * F + lane * 4));
        float2 f0 = __half22float2(*reinterpret_cast<__half2*>(&r.x));
        float2 f1 = __half22float2(*reinterpret_cast<__half2*>(&r.y));
        acc.x = di * f0.x; acc.y = di * f0.y;
        acc.z = di * f1.x; acc.w = di * f1.y;
    }

    int beg = g_rowptr[node];
    int end = g_cnt[node];
    for (int base = beg; base < end; base += 32) {
        int n = end - base;
        if (n > 32) n = 32;
        if (lane < n) {
            int2 e = __ldg(&g_edge[base + lane]);
            sSrc[warp][lane] = e.x;
            sWt[warp][lane]  = __int_as_float(e.y);
        }
        __syncwarp();
        int t = 0;
        for (; t + 4 <= n; t += 4) {
            int s0 = sSrc[warp][t],     s1 = sSrc[warp][t + 1];
            int s2 = sSrc[warp][t + 2], s3 = sSrc[warp][t + 3];
            float w0 = sWt[warp][t],     w1 = sWt[warp][t + 1];
            float w2 = sWt[warp][t + 2], w3 = sWt[warp][t + 3];
            uint2 r0 = __ldg((const uint2*)(in16 + (size_t)s0 * F + lane * 4));
            uint2 r1 = __ldg((const uint2*)(in16 + (size_t)s1 * F + lane * 4));
            uint2 r2 = __ldg((const uint2*)(in16 + (size_t)s2 * F + lane * 4));
            uint2 r3 = __ldg((const uint2*)(in16 + (size_t)s3 * F + lane * 4));
            float2 a0 = __half22float2(*reinterpret_cast<__half2*>(&r0.x));
            float2 b0 = __half22float2(*reinterpret_cast<__half2*>(&r0.y));
            acc.x = fmaf(w0, a0.x, acc.x); acc.y = fmaf(w0, a0.y, acc.y);
            acc.z = fmaf(w0, b0.x, acc.z); acc.w = fmaf(w0, b0.y, acc.w);
            float2 a1 = __half22float2(*reinterpret_cast<__half2*>(&r1.x));
            float2 b1 = __half22float2(*reinterpret_cast<__half2*>(&r1.y));
            acc.x = fmaf(w1, a1.x, acc.x); acc.y = fmaf(w1, a1.y, acc.y);
            acc.z = fmaf(w1, b1.x, acc.z); acc.w = fmaf(w1, b1.y, acc.w);
            float2 a2 = __half22float2(*reinterpret_cast<__half2*>(&r2.x));
            float2 b2 = __half22float2(*reinterpret_cast<__half2*>(&r2.y));
            acc.x = fmaf(w2, a2.x, acc.x); acc.y = fmaf(w2, a2.y, acc.y);
            acc.z = fmaf(w2, b2.x, acc.z); acc.w = fmaf(w2, b2.y, acc.w);
            float2 a3 = __half22float2(*reinterpret_cast<__half2*>(&r3.x));
            float2 b3 = __half22float2(*reinterpret_cast<__half2*>(&r3.y));
            acc.x = fmaf(w3, a3.x, acc.x); acc.y = fmaf(w3, a3.y, acc.y);
            acc.z = fmaf(w3, b3.x, acc.z); acc.w = fmaf(w3, b3.y, acc.w);
        }
        for (; t < n; t++) {
            int s  = sSrc[warp][t];
            float w = sWt[warp][t];
            uint2 r = __ldg((const uint2*)(in16 + (size_t)s * F + lane * 4));
            float2 a = __half22float2(*reinterpret_cast<__half2*>(&r.x));
            float2 b = __half22float2(*reinterpret_cast<__half2*>(&r.y));
            acc.x = fmaf(w, a.x, acc.x); acc.y = fmaf(w, a.y, acc.y);
            acc.z = fmaf(w, b.x, acc.z); acc.w = fmaf(w, b.y, acc.w);
        }
        __syncwarp();
    }

    __half2 h0 = __floats2half2_rn(acc.x * di, acc.y * di);
    __half2 h1 = __floats2half2_rn(acc.z * di, acc.w * di);
    uint2 r;
    r.x = *reinterpret_cast<unsigned*>(&h0);
    r.y = *reinterpret_cast<unsigned*>(&h1);
    *reinterpret_cast<uint2*>(&g_t16[(size_t)node * F + lane * 4]) = r;
}

// ---------------- WMMA GEMM: relu(A16[M,128] @ W16[128,128] + b) -------------
// 32x128 block tile, 8 warps (2 on M x 4 on N), warp tile 16x32.
// Padded smem rows (LDH=136 halves / LDC=132 floats) -> conflict-free ldsm/C.
__global__ void __launch_bounds__(256) k_hgemm_store(const __half* __restrict__ A,
                                                     const __half* __restrict__ Wh,
                                                     const float* __restrict__ bias,
                                                     __half* __restrict__ Out, int M) {
    __shared__ __half sA[32 * LDH];   //  8.7 KB
    __shared__ __half sW[F * LDH];    // 34.8 KB, reused as C (32 x LDC fp32)

    const int tid = threadIdx.x;
    const int bm  = blockIdx.x * 32;

    for (int it = 0; it < 2; it++) {
        int idx = tid + it * 256;
        int r   = idx >> 4;
        int c8  = idx & 15;
        uint4 v = make_uint4(0, 0, 0, 0);
        int gr = bm + r;
        if (gr < M) v = *(const uint4*)&A[(size_t)gr * F + c8 * 8];
        *(uint4*)&sA[r * LDH + c8 * 8] = v;
    }
    for (int it = 0; it < 8; it++) {
        int idx = tid + it * 256;
        int r   = idx >> 4;
        int c8  = idx & 15;
        *(uint4*)&sW[r * LDH + c8 * 8] = *(const uint4*)&Wh[r * F + c8 * 8];
    }
    __syncthreads();

    const int warp = tid >> 5;
    const int wm = (warp & 1) * 16;        // 0,16
    const int wn = (warp >> 1) * 32;       // 0,32,64,96

    wmma::fragment<wmma::accumulator, 16, 16, 16, float> c0, c1;
    wmma::fill_fragment(c0, 0.0f);
    wmma::fill_fragment(c1, 0.0f);

    for (int k0 = 0; k0 < F; k0 += 16) {
        wmma::fragment<wmma::matrix_a, 16, 16, 16, __half, wmma::row_major> a;
        wmma::load_matrix_sync(a, &sA[wm * LDH + k0], LDH);
        wmma::fragment<wmma::matrix_b, 16, 16, 16, __half, wmma::row_major> b;
        wmma::load_matrix_sync(b, &sW[k0 * LDH + wn], LDH);
        wmma::mma_sync(c0, a, b, c0);
        wmma::load_matrix_sync(b, &sW[k0 * LDH + wn + 16], LDH);
        wmma::mma_sync(c1, a, b, c1);
    }

    __syncthreads();
    float* sC = reinterpret_cast<float*>(sW);   // 32 x LDC fp32
    wmma::store_matrix_sync(&sC[wm * LDC + wn],      c0, LDC, wmma::mem_row_major);
    wmma::store_matrix_sync(&sC[wm * LDC + wn + 16], c1, LDC, wmma::mem_row_major);
    __syncthreads();

    for (int it = 0; it < 4; it++) {
        int idx = tid + it * 256;
        int row = idx >> 5;
        int c4  = idx & 31;
        int gr  = bm + row;
        if (gr < M) {
            float4 v  = *(float4*)&sC[row * LDC + c4 * 4];
            float4 bb = *(const float4*)&bias[c4 * 4];
            __half2 h0 = __floats2half2_rn(fmaxf(v.x + bb.x, 0.0f),
                                           fmaxf(v.y + bb.y, 0.0f));
            __half2 h1 = __floats2half2_rn(fmaxf(v.z + bb.z, 0.0f),
                                           fmaxf(v.w + bb.w, 0.0f));
            uint2 r;
            r.x = *reinterpret_cast<unsigned*>(&h0);
            r.y = *reinterpret_cast<unsigned*>(&h1);
            *reinterpret_cast<uint2*>(&Out[(size_t)gr * F + c4 * 4]) = r;
        }
    }
}

__global__ void __launch_bounds__(256) k_hgemm_pool(const __half* __restrict__ A,
                                                    const __half* __restrict__ Wh,
                                                    const float* __restrict__ bias,
                                                    int M) {
    __shared__ __half sA[32 * LDH];
    __shared__ __half sW[F * LDH];    // reused as C

    const int tid = threadIdx.x;
    const int bm  = blockIdx.x * 32;

    for (int it = 0; it < 2; it++) {
        int idx = tid + it * 256;
        int r   = idx >> 4;
        int c8  = idx & 15;
        uint4 v = make_uint4(0, 0, 0, 0);
        int gr = bm + r;
        if (gr < M) v = *(const uint4*)&A[(size_t)gr * F + c8 * 8];
        *(uint4*)&sA[r * LDH + c8 * 8] = v;
    }
    for (int it = 0; it < 8; it++) {
        int idx = tid + it * 256;
        int r   = idx >> 4;
        int c8  = idx & 15;
        *(uint4*)&sW[r * LDH + c8 * 8] = *(const uint4*)&Wh[r * F + c8 * 8];
    }
    __syncthreads();

    const int warp = tid >> 5;
    const int wm = (warp & 1) * 16;
    const int wn = (warp >> 1) * 32;

    wmma::fragment<wmma::accumulator, 16, 16, 16, float> c0, c1;
    wmma::fill_fragment(c0, 0.0f);
    wmma::fill_fragment(c1, 0.0f);

    for (int k0 = 0; k0 < F; k0 += 16) {
        wmma::fragment<wmma::matrix_a, 16, 16, 16, __half, wmma::row_major> a;
        wmma::load_matrix_sync(a, &sA[wm * LDH + k0], LDH);
        wmma::fragment<wmma::matrix_b, 16, 16, 16, __half, wmma::row_major> b;
        wmma::load_matrix_sync(b, &sW[k0 * LDH + wn], LDH);
        wmma::mma_sync(c0, a, b, c0);
        wmma::load_matrix_sync(b, &sW[k0 * LDH + wn + 16], LDH);
        wmma::mma_sync(c1, a, b, c1);
    }

    __syncthreads();
    float* sC = reinterpret_cast<float*>(sW);
    wmma::store_matrix_sync(&sC[wm * LDC + wn],      c0, LDC, wmma::mem_row_major);
    wmma::store_matrix_sync(&sC[wm * LDC + wn + 16], c1, LDC, wmma::mem_row_major);
    __syncthreads();

    int rowmax = M - bm;
    if (rowmax > 32) rowmax = 32;
    if (tid < F) {
        float bb = bias[tid];
        float s = 0.0f;
        for (int row = 0; row < rowmax; row++)
            s += fmaxf(sC[row * LDC + tid] + bb, 0.0f);
        atomicAdd(&g_pool[tid], s);
    }
}

// ---------------- FC ---------------------------------------------------------
__global__ void k_fc(const float* __restrict__ fw, const float* __restrict__ fb,
                     float* __restrict__ out) {
    int jj = threadIdx.x;
    if (jj < 2) {
        const float inv_n = 1.0f / (float)N_NODES;
        float s = 0.0f;
        for (int k = 0; k < F; k++)
            s += g_pool[k] * inv_n * fw[k * 2 + jj];
        out[jj] = s + fb[jj];
    }
}

// ---------------- launch -----------------------------------------------------
extern "C" void kernel_launch(void* const* d_in, const int* in_sizes, int n_in,
                              void* d_out, int out_size) {
    const float* x   = (const float*)d_in[0];
    const int*   ei  = (const int*)d_in[1];
    const float* W1  = (const float*)d_in[2];
    const float* b1  = (const float*)d_in[3];
    const float* W2  = (const float*)d_in[4];
    const float* b2  = (const float*)d_in[5];
    const float* W3  = (const float*)d_in[6];
    const float* b3  = (const float*)d_in[7];
    const float* fcw = (const float*)d_in[8];
    const float* fcb = (const float*)d_in[9];
    float* out = (float*)d_out;

    const int* e_src = ei;
    const int* e_dst = ei + N_EDGES;

    __half *t16, *f16, *w16;
    cudaGetSymbolAddress((void**)&t16, g_t16);
    cudaGetSymbolAddress((void**)&f16, g_feat16);
    cudaGetSymbolAddress((void**)&w16, g_w16);

    // ---- conversions + zero (fused) ----
    k_cvt<<<(N_NODES * 32 + 255) / 256, 256>>>(x);
    k_cvtW3<<<(3 * F * F / 4 + 255) / 256, 256>>>(W1, W2, W3);

    // ---- CSR build ----
    k_hist<<<(N_EDGES + 255) / 256, 256>>>(e_dst);
    k_scanA<<<(NCHUNK * 32 + 255) / 256, 256>>>();
    k_scanB<<<1, 1024>>>();
    k_scanC<<<(NCHUNK * 32 + 255) / 256, 256>>>();
    k_fill<<<(N_EDGES + 255) / 256, 256>>>(e_src, e_dst);

    const int gemm_grid = (N_NODES + 31) / 32;
    const int agg_grid  = (N_NODES + 7) / 8;

    // layer 1
    k_agg<<<agg_grid, 256>>>();
    k_hgemm_store<<<gemm_grid, 256>>>(t16, w16 + 0 * F * F, b1, f16, N_NODES);
    // layer 2
    k_agg<<<agg_grid, 256>>>();
    k_hgemm_store<<<gemm_grid, 256>>>(t16, w16 + 1 * F * F, b2, f16, N_NODES);
    // layer 3 (pool fused into epilogue)
    k_agg<<<agg_grid, 256>>>();
    k_hgemm_pool<<<gemm_grid, 256>>>(t16, w16 + 2 * F * F, b3, N_NODES);

    k_fc<<<1, 32>>>(fcw, fcb, out);
}